// round 8
// baseline (speedup 1.0000x reference)
#include <cuda_runtime.h>

// BlurOutwards: out = (1/20) * sum_{i=0}^{19} D^i(x), D = 3x3 max, zero padding.
// Iterated zero-padded dilation == iterated 3x3 max on the zero-extended image;
// composes across passes: D^{a+b}(x) = D^b(D^a(x)).
//
// Three chained register-pipeline passes (7 + 7 + 5 levels), 2 px/thread:
//   - TPB=256 threads each own a float2 column pair; 1 SHFL per px per level.
//   - warp-edge columns via tiny double-buffered smem with zero guard slots.

#define IMH   512
#define IMW   512
#define TPB   256
#define NW    (TPB / 32)         // 8 warps
#define SEGS  3
#define MAX_PLANES 96

// Static scratch for intermediate dilation planes (y7, y14).
__device__ float g_scrA[MAX_PLANES * IMH * IMW];
__device__ float g_scrB[MAX_PLANES * IMH * IMW];

template<int NLEV, bool FIRST, bool WRITE_Y, bool FINAL>
__global__ __launch_bounds__(TPB, 2)
void blur_pass_kernel(const float* __restrict__ in,
                      const float* sum_in,
                      float* sum_out,
                      float* __restrict__ y_out)
{
    const int plane = blockIdx.x;
    const int seg   = blockIdx.y;

    const int r0 = (IMH * seg) / SEGS;
    const int r1 = (IMH * (seg + 1)) / SEGS;

    const size_t pbase = (size_t)plane * IMH * IMW;
    const float2* ip  = (const float2*)(in + pbase);

    const int tid  = threadIdx.x;          // pair index: columns 2*tid, 2*tid+1
    const int lane = tid & 31;
    const int warp = tid >> 5;

    // Double-buffered warp-edge exchange with zero guard slots:
    //   eR[par][i][w+1] = rightmost px (lane31.p1) of warp w;  eR[..][0]    == 0
    //   eL[par][i][w+1] = leftmost  px (lane0.p0)  of warp w;  eL[..][NW+1] == 0
    __shared__ float eR[2][NLEV][NW + 2];
    __shared__ float eL[2][NLEV][NW + 2];
    for (int k = tid; k < 2 * NLEV * (NW + 2); k += TPB) {
        (&eR[0][0][0])[k] = 0.0f;
        (&eL[0][0][0])[k] = 0.0f;
    }
    __syncthreads();

    // Per-level pipeline state, per pixel (a = even col, b = odd col).
    float pa[NLEV], pb[NLEV];       // buffered raw row awaiting horizontal pass
    float h1a[NLEV], h1b[NLEV];     // h of previous row
    float mxa[NLEV], mxb[NLEV];     // max of prior two h-rows
    float d1a[NLEV], d1b[NLEV];     // sum delay regs (2-deep)
    float d2a[NLEV], d2b[NLEV];
#pragma unroll
    for (int i = 0; i < NLEV; ++i) {
        pa[i]=0.f; pb[i]=0.f; h1a[i]=0.f; h1b[i]=0.f; mxa[i]=0.f; mxb[i]=0.f;
        d1a[i]=0.f; d1b[i]=0.f; d2a[i]=0.f; d2b[i]=0.f;
    }

    const int DELAY = 2 * NLEV;
    const int t0    = r0 - NLEV;           // exact warmup
    const int tend  = r1 - 1 + DELAY;

    const bool isL = (lane == 0);
    const bool isR = (lane == 31);

    for (int t = t0; t <= tend; ++t) {
        const int par = (t - t0) & 1;
        const int nxt = par ^ 1;

        float v0 = 0.0f, v1 = 0.0f;
        if ((unsigned)t < (unsigned)IMH) {
            float2 v = __ldg(&ip[(size_t)t * (IMW / 2) + tid]);
            v0 = v.x; v1 = v.y;
        }

        float in0 = v0, in1 = v1;                     // y_{i-1} handoff
        float sp0 = FIRST ? v0 : 0.0f;                // sum pipeline input
        float sp1 = FIRST ? v1 : 0.0f;

#pragma unroll
        for (int i = 0; i < NLEV; ++i) {
            // Horizontal 3-max on the one-row-stale buffered pair.
            float p0 = pa[i], p1 = pb[i];
            float l = __shfl_up_sync(0xffffffffu, p1, 1);   // left neighbor's p1
            float r = __shfl_down_sync(0xffffffffu, p0, 1); // right neighbor's p0
            if (isL) l = eR[par][i][warp];        // cross-warp (0 at image edge)
            if (isR) r = eL[par][i][warp + 2];
            float m  = fmaxf(p0, p1);
            float h0 = fmaxf(l, m);
            float h1 = fmaxf(m, r);

            // Vertical 3-max (centered one row back).
            float y0 = fmaxf(mxa[i], h0);
            mxa[i] = fmaxf(h1a[i], h0);
            h1a[i] = h0;
            float y1 = fmaxf(mxb[i], h1);
            mxb[i] = fmaxf(h1b[i], h1);
            h1b[i] = h1;

            // Sum pipeline with 2-row delay alignment.
            float s0 = d2a[i] + y0;  d2a[i] = d1a[i];  d1a[i] = sp0;
            float s1 = d2b[i] + y1;  d2b[i] = d1b[i];  d1b[i] = sp1;

            // Hand-offs.
            pa[i] = in0;  pb[i] = in1;
            if (isL) eL[nxt][i][warp + 1] = in0;
            if (isR) eR[nxt][i][warp + 1] = in1;
            in0 = y0;  in1 = y1;
            sp0 = s0;  sp1 = s1;
        }

        const int orow = t - DELAY;
        if (orow >= r0 && orow < r1) {
            const size_t pidx = pbase / 2 + (size_t)orow * (IMW / 2) + tid;
            float s0 = sp0, s1 = sp1;
            if (!FIRST) {
                float2 acc = __ldg(&((const float2*)sum_in)[pidx]);
                s0 += acc.x;  s1 += acc.y;
            }
            float2 o;
            if (FINAL) { o.x = s0 * 0.05f; o.y = s1 * 0.05f; }
            else       { o.x = s0;          o.y = s1; }
            ((float2*)sum_out)[pidx] = o;
            if (WRITE_Y) {
                float2 yo; yo.x = in0; yo.y = in1;   // == y_NLEV[orow]
                ((float2*)y_out)[pidx] = yo;
            }
        }

        __syncthreads();  // separates this step's edge writes from next reads
    }
}

extern "C" void kernel_launch(void* const* d_in, const int* in_sizes, int n_in,
                              void* d_out, int out_size)
{
    const float* in = (const float*)d_in[0];
    float* out      = (float*)d_out;

    const int planes = in_sizes[0] / (IMH * IMW);   // 96

    float *scrA = nullptr, *scrB = nullptr;
    cudaGetSymbolAddress((void**)&scrA, g_scrA);
    cudaGetSymbolAddress((void**)&scrB, g_scrB);

    dim3 grid(planes, SEGS);

    // Pass 1: levels 1..7 (+ identity term), writes s(0..7) and y7.
    blur_pass_kernel<7, true,  true,  false><<<grid, TPB>>>(in,   nullptr, out, scrA);
    // Pass 2: levels 8..14, accumulates into out, writes y14.
    blur_pass_kernel<7, false, true,  false><<<grid, TPB>>>(scrA, out,     out, scrB);
    // Pass 3: levels 15..19, accumulates and scales by 1/20.
    blur_pass_kernel<5, false, false, true ><<<grid, TPB>>>(scrB, out,     out, nullptr);
}